// round 9
// baseline (speedup 1.0000x reference)
#include <cuda_runtime.h>
#include <cuda_bf16.h>
#include <math.h>

// Problem constants
#define BATCH   8
#define OCH     512
#define HW      4096      // 64*64
#define NPLANES (BATCH*OCH)

// Scratch (device globals; no allocation allowed)
__device__ float g_z   [BATCH*OCH*HW];   // 64 MB: z = relu(g_conv(g)) + x_conv(x)
__device__ float g_phi [BATCH*OCH*HW];   // 64 MB: phi0 = c_conv(contour)
__device__ float g_gwT [256*512];        // transposed weights [K][O]
__device__ float g_xwT [512*512];
__device__ float g_cwT [256*512];

// ---------------------------------------------------------------------------
// Packed f32x2 helpers. On sm_100+ use fma.rn.f32x2 (FFMA2: halves fma-pipe
// instruction count vs 3-reg FFMA; ptxas never auto-fuses, so inline PTX is
// required). On any other target fall back to two scalar fmaf — correct but
// slower, so an unexpected arch flag degrades instead of failing the build.
// ---------------------------------------------------------------------------
__device__ __forceinline__ unsigned long long pack2(float x, float y) {
    unsigned long long r;
    asm("mov.b64 %0, {%1, %2};" : "=l"(r) : "f"(x), "f"(y));
    return r;
}
__device__ __forceinline__ void unpack2(unsigned long long v, float& x, float& y) {
    asm("mov.b64 {%0, %1}, %2;" : "=f"(x), "=f"(y) : "l"(v));
}
__device__ __forceinline__ void fma2(unsigned long long& d,
                                     unsigned long long a,
                                     unsigned long long b) {
#if defined(__CUDA_ARCH__) && (__CUDA_ARCH__ >= 1000)
    asm("fma.rn.f32x2 %0, %1, %2, %0;" : "+l"(d) : "l"(a), "l"(b));
#else
    float dx, dy, ax, ay, bx, by;
    unpack2(d, dx, dy); unpack2(a, ax, ay); unpack2(b, bx, by);
    d = pack2(fmaf(ax, bx, dx), fmaf(ay, by, dy));
#endif
}

// ---------------------------------------------------------------------------
// Fused weight transpose: w[O][K] -> wt[K][O] for all three weight matrices.
// blockIdx.y selects the matrix.
// ---------------------------------------------------------------------------
__global__ void transpose_w_all(const float* __restrict__ g_w,
                                const float* __restrict__ x_w,
                                const float* __restrict__ c_w,
                                float* __restrict__ gwT,
                                float* __restrict__ xwT,
                                float* __restrict__ cwT) {
    int which = blockIdx.y;
    const float* w = (which == 0) ? g_w : (which == 1) ? x_w : c_w;
    float* wt      = (which == 0) ? gwT : (which == 1) ? xwT : cwT;
    int K          = (which == 1) ? 512 : 256;
    int i = blockIdx.x * blockDim.x + threadIdx.x;
    if (i < 512 * K) {
        int o = i / K, k = i % K;
        wt[k * 512 + o] = w[i];
    }
}

// ---------------------------------------------------------------------------
// Fused 1x1 convs as batched GEMM:  Out[b][o][p] = sum_k wT[k][o]*In[b][k][p]
// blockIdx.y in [0,8): y<4 -> z = relu(gw.g)+xw.x (two passes); y>=4 -> phi0.
// Tile 128(o) x 128(p) x 16(k); 256 threads; 8(o) x 8(p) outputs per thread,
// p-values held as 4 packed f32x2 accumulators -> 32 FFMA2 per k-slice.
// ---------------------------------------------------------------------------
__global__ __launch_bounds__(256)
void conv1x1_fused(const float* __restrict__ g,       const float* __restrict__ gwT,
                   const float* __restrict__ x,       const float* __restrict__ xwT,
                   const float* __restrict__ contour, const float* __restrict__ cwT,
                   float* __restrict__ zout, float* __restrict__ pout)
{
    __shared__ float sW[16 * 128];
    __shared__ float sI[16 * 128];

    const int tid = threadIdx.x;
    const int tx = tid & 15;       // p sub-tile (8 pixels = 4 packed pairs)
    const int ty = tid >> 4;       // o sub-tile
    const int pT = blockIdx.x * 128;
    const int b  = blockIdx.z;
    const int isZ = (blockIdx.y < 4);
    const int oT  = (isZ ? blockIdx.y : blockIdx.y - 4) * 128;

    const float* inA = isZ ? g   : contour;
    const float* wAT = isZ ? gwT : cwT;
    const int KA     = 256;
    const int doRelu = isZ;
    const float* inB = isZ ? x   : (const float*)0;
    const float* wBT = isZ ? xwT : (const float*)0;
    const int KB     = isZ ? 512 : 0;
    float* out       = isZ ? zout : pout;

    unsigned long long acc[8][4];
#pragma unroll
    for (int i = 0; i < 8; i++)
#pragma unroll
        for (int j = 0; j < 4; j++) acc[i][j] = 0ull;

#pragma unroll 1
    for (int pass = 0; pass < 2; pass++) {
        const float* in = pass ? inB : inA;
        const float* wT = pass ? wBT : wAT;
        const int K = pass ? KB : KA;
        if (K == 0) break;
        const float* inb = in + (size_t)b * K * HW;

#pragma unroll 1
        for (int k0 = 0; k0 < K; k0 += 16) {
            __syncthreads();
            // Load 16x128 tiles (coalesced float4)
#pragma unroll
            for (int r = 0; r < 2; r++) {
                int lin = tid + r * 256;              // 0..511
                int kl = lin >> 5;                    // 0..15
                int c4 = (lin & 31) * 4;              // 0..124
                *(float4*)&sW[kl * 128 + c4] = *(const float4*)&wT[(k0 + kl) * 512 + oT + c4];
                *(float4*)&sI[kl * 128 + c4] = *(const float4*)&inb[(size_t)(k0 + kl) * HW + pT + c4];
            }
            __syncthreads();
#pragma unroll
            for (int kk = 0; kk < 16; kk++) {
                // a: 8 o-values; broadcast smem reads (conflict-free)
                float4 a0 = *(float4*)&sW[kk * 128 + ty * 8];
                float4 a1 = *(float4*)&sW[kk * 128 + ty * 8 + 4];
                float av[8] = {a0.x, a0.y, a0.z, a0.w, a1.x, a1.y, a1.z, a1.w};
                // b: 8 consecutive p-values = 4 packed f32x2 pairs
                const ulonglong2* bp = (const ulonglong2*)&sI[kk * 128 + tx * 8];
                ulonglong2 b01 = bp[0];
                ulonglong2 b23 = bp[1];
                unsigned long long bv[4] = {b01.x, b01.y, b23.x, b23.y};
#pragma unroll
                for (int i = 0; i < 8; i++) {
                    unsigned long long ai = pack2(av[i], av[i]);
#pragma unroll
                    for (int j = 0; j < 4; j++)
                        fma2(acc[i][j], ai, bv[j]);
                }
            }
        }
        if (pass == 0 && doRelu) {
#pragma unroll
            for (int i = 0; i < 8; i++)
#pragma unroll
                for (int j = 0; j < 4; j++) {
                    float lo, hi;
                    unpack2(acc[i][j], lo, hi);
                    acc[i][j] = pack2(fmaxf(lo, 0.f), fmaxf(hi, 0.f));
                }
        }
    }

#pragma unroll
    for (int i = 0; i < 8; i++) {
        int o = oT + ty * 8 + i;
        float* orow = out + ((size_t)b * OCH + o) * HW + pT + tx * 8;
        ulonglong2 s0; s0.x = acc[i][0]; s0.y = acc[i][1];
        ulonglong2 s1; s1.x = acc[i][2]; s1.y = acc[i][3];
        *(ulonglong2*)&orow[0] = s0;
        *(ulonglong2*)&orow[4] = s1;
    }
}

// ---------------------------------------------------------------------------
// Block reductions over 256 threads (8 warps)
// ---------------------------------------------------------------------------
__device__ __forceinline__ float breduce1(float v, float* red) {
#pragma unroll
    for (int o = 16; o; o >>= 1) v += __shfl_xor_sync(0xffffffffu, v, o);
    int w = threadIdx.x >> 5;
    __syncthreads();
    if ((threadIdx.x & 31) == 0) red[w] = v;
    __syncthreads();
    float s = 0.f;
#pragma unroll
    for (int i = 0; i < 8; i++) s += red[i];
    return s;
}

__device__ __forceinline__ void breduce2(float& a, float& b, float* red) {
#pragma unroll
    for (int o = 16; o; o >>= 1) {
        a += __shfl_xor_sync(0xffffffffu, a, o);
        b += __shfl_xor_sync(0xffffffffu, b, o);
    }
    int w = threadIdx.x >> 5;
    __syncthreads();              // also the cross-iteration phi/nx/ny hazard barrier
    if ((threadIdx.x & 31) == 0) { red[w] = a; red[w + 8] = b; }
    __syncthreads();
    float sa = 0.f, sb = 0.f;
#pragma unroll
    for (int i = 0; i < 8; i++) { sa += red[i]; sb += red[i + 8]; }
    a = sa; b = sb;
}

// ---------------------------------------------------------------------------
// Chan-Vese: one CTA owns one 64x64 plane; phi/nx/ny resident in SMEM for all
// 10 iterations (zero HBM traffic inside the loop); each thread's 16 z-values
// live in REGISTERS (z is only ever read at own pixels -> needn't be shared).
// smem = 3 planes + scratch = 49.4 KB -> 4 CTAs/SM.
// jnp.gradient semantics: one-sided at edges, central/2 inside (clamped
// neighbor + scale). Data term folded: -lam(I-c1)^2+lam(I-c2)^2 = A*I + B.
// ---------------------------------------------------------------------------
__global__ __launch_bounds__(256)
void cv_kernel(const float* __restrict__ phi0, const float* __restrict__ z,
               const float* __restrict__ dtp, const float* __restrict__ lamp,
               float* __restrict__ out)
{
    extern __shared__ float sm[];
    float* phi = sm;
    float* nx  = sm + 4096;
    float* ny  = sm + 8192;
    float* red = sm + 12288;   // 64 floats scratch

    const int tid = threadIdx.x;
    const size_t base = (size_t)blockIdx.x * HW;
    const float dt  = dtp[0];
    const float lam = lamp[0];
    const float INV_PI = 0.3183098861837907f;

    float zr[16];              // own z pixels, register-resident
    float sI = 0.f;
#pragma unroll
    for (int k = 0; k < 16; k++) {
        int p = tid + k * 256;
        float zv = z[base + p];
        phi[p] = phi0[base + p];
        zr[k] = zv;
        sI += zv;
    }
    float sumI = breduce1(sI, red);

#pragma unroll 1
    for (int it = 0; it < 10; it++) {
        // --- region statistics: sum(H), sum(I*H) (own pixels only) ---
        float sH = 0.f, sIH = 0.f;
#pragma unroll
        for (int k = 0; k < 16; k++) {
            int p = tid + k * 256;
            float ph = phi[p];
            float Hh = fmaf(INV_PI, atanf(ph), 0.5f);   // 0.5*(1 + (2/pi)*atan)
            sH  += Hh;
            sIH += zr[k] * Hh;
        }
        breduce2(sH, sIH, red);
        float c1 = sIH / (sH + 1e-8f);
        float c2 = (sumI - sIH) / (4096.0f - sH + 1e-8f);
        float A  = 2.0f * lam * (c1 - c2);
        float Bc = lam * (c2 * c2 - c1 * c1);

        // --- normalized gradient field nx, ny ---
#pragma unroll
        for (int k = 0; k < 16; k++) {
            int p = tid + k * 256;
            int w = p & 63, u = p >> 6;
            float c  = phi[p];
            float l  = w          ? phi[p - 1]  : c;
            float r  = (w != 63)  ? phi[p + 1]  : c;
            float d  = u          ? phi[p - 64] : c;
            float up = (u != 63)  ? phi[p + 64] : c;
            float sx = (w == 0 || w == 63) ? 1.f : 0.5f;
            float sy = (u == 0 || u == 63) ? 1.f : 0.5f;
            float px = sx * (r - l);
            float py = sy * (up - d);
            float inv = rsqrtf(fmaf(px, px, fmaf(py, py, 1e-8f)));
            nx[p] = px * inv;
            ny[p] = py * inv;
        }
        __syncthreads();

        // --- curvature + update (phi[p] written only by its owner) ---
#pragma unroll
        for (int k = 0; k < 16; k++) {
            int p = tid + k * 256;
            int w = p & 63, u = p >> 6;
            float cx = nx[p], cy = ny[p];
            float l  = w          ? nx[p - 1]  : cx;
            float r  = (w != 63)  ? nx[p + 1]  : cx;
            float d  = u          ? ny[p - 64] : cy;
            float up = (u != 63)  ? ny[p + 64] : cy;
            float sx = (w == 0 || w == 63) ? 1.f : 0.5f;
            float sy = (u == 0 || u == 63) ? 1.f : 0.5f;
            float curv = sx * (r - l) + sy * (up - d);
            float ph = phi[p];
            float delta = INV_PI / fmaf(ph, ph, 1.0f);   // EPS_H = 1
            float force = curv + fmaf(A, zr[k], Bc);
            phi[p] = fmaf(dt * delta, force, ph);
        }
        // next iteration's breduce2 __syncthreads() separates this phi write
        // from the next gradient pass's neighbor reads.
    }

    __syncthreads();
#pragma unroll
    for (int k = 0; k < 16; k++) {
        int p = tid + k * 256;
        float ph = phi[p];
        out[base + p] = 1.0f / (1.0f + expf(-ph));
    }
}

// ---------------------------------------------------------------------------
// Launch
// ---------------------------------------------------------------------------
extern "C" void kernel_launch(void* const* d_in, const int* in_sizes, int n_in,
                              void* d_out, int out_size)
{
    const float* contour = (const float*)d_in[0];   // [8,256,64,64]
    const float* g       = (const float*)d_in[1];   // [8,256,64,64]
    const float* x       = (const float*)d_in[2];   // [8,512,64,64]
    const float* dt      = (const float*)d_in[3];   // [1]
    const float* lam     = (const float*)d_in[4];   // [1]
    const float* g_w     = (const float*)d_in[5];   // [512,256]
    const float* x_w     = (const float*)d_in[6];   // [512,512]
    const float* c_w     = (const float*)d_in[7];   // [512,256]
    float* out = (float*)d_out;                     // [8,512,64,64]

    float *zbuf, *phibuf, *gwT, *xwT, *cwT;
    cudaGetSymbolAddress((void**)&zbuf,   g_z);
    cudaGetSymbolAddress((void**)&phibuf, g_phi);
    cudaGetSymbolAddress((void**)&gwT,    g_gwT);
    cudaGetSymbolAddress((void**)&xwT,    g_xwT);
    cudaGetSymbolAddress((void**)&cwT,    g_cwT);

    // All three weight transposes in one launch
    dim3 tgrid((512 * 512 + 255) / 256, 3);
    transpose_w_all<<<tgrid, 256>>>(g_w, x_w, c_w, gwT, xwT, cwT);

    // Both 1x1-conv GEMMs in one launch: y<4 -> z, y>=4 -> phi0
    dim3 grid(HW / 128, 8, BATCH);   // 32 x 8 x 8 = 2048 CTAs
    conv1x1_fused<<<grid, 256>>>(g, gwT, x, xwT, contour, cwT, zbuf, phibuf);

    int smem = (3 * 4096 + 64) * (int)sizeof(float);   // 49,408 B -> 4 CTAs/SM
    cudaFuncSetAttribute(cv_kernel, cudaFuncAttributeMaxDynamicSharedMemorySize, smem);
    cv_kernel<<<NPLANES, 256, smem>>>(phibuf, zbuf, dt, lam, out);
}

// round 15
// speedup vs baseline: 1.2026x; 1.2026x over previous
#include <cuda_runtime.h>
#include <cuda_bf16.h>
#include <math.h>

// Problem constants
#define BATCH   8
#define OCH     512
#define HW      4096      // 64*64
#define NPLANES (BATCH*OCH)

// Scratch (device globals; no allocation allowed)
__device__ float g_z   [BATCH*OCH*HW];   // 64 MB: z = relu(g_conv(g)) + x_conv(x)
__device__ float g_phi [BATCH*OCH*HW];   // 64 MB: phi0 = c_conv(contour)
__device__ float g_gwT [256*512];        // transposed weights [K][O]
__device__ float g_xwT [512*512];
__device__ float g_cwT [256*512];

// ---------------------------------------------------------------------------
// Packed f32x2 helpers. On sm_100+ use fma.rn.f32x2 (FFMA2: halves fma-pipe
// instruction count vs 3-reg FFMA; ptxas never auto-fuses, so inline PTX is
// required). Fallback keeps other targets compiling.
// ---------------------------------------------------------------------------
__device__ __forceinline__ unsigned long long pack2(float x, float y) {
    unsigned long long r;
    asm("mov.b64 %0, {%1, %2};" : "=l"(r) : "f"(x), "f"(y));
    return r;
}
__device__ __forceinline__ void unpack2(unsigned long long v, float& x, float& y) {
    asm("mov.b64 {%0, %1}, %2;" : "=f"(x), "=f"(y) : "l"(v));
}
__device__ __forceinline__ void fma2(unsigned long long& d,
                                     unsigned long long a,
                                     unsigned long long b) {
#if defined(__CUDA_ARCH__) && (__CUDA_ARCH__ >= 1000)
    asm("fma.rn.f32x2 %0, %1, %2, %0;" : "+l"(d) : "l"(a), "l"(b));
#else
    float dx, dy, ax, ay, bx, by;
    unpack2(d, dx, dy); unpack2(a, ax, ay); unpack2(b, bx, by);
    d = pack2(fmaf(ax, bx, dx), fmaf(ay, by, dy));
#endif
}

// ---------------------------------------------------------------------------
// Fused weight transpose: w[O][K] -> wt[K][O] for all three weight matrices.
// ---------------------------------------------------------------------------
__global__ void transpose_w_all(const float* __restrict__ g_w,
                                const float* __restrict__ x_w,
                                const float* __restrict__ c_w,
                                float* __restrict__ gwT,
                                float* __restrict__ xwT,
                                float* __restrict__ cwT) {
    int which = blockIdx.y;
    const float* w = (which == 0) ? g_w : (which == 1) ? x_w : c_w;
    float* wt      = (which == 0) ? gwT : (which == 1) ? xwT : cwT;
    int K          = (which == 1) ? 512 : 256;
    int i = blockIdx.x * blockDim.x + threadIdx.x;
    if (i < 512 * K) {
        int o = i / K, k = i % K;
        wt[k * 512 + o] = w[i];
    }
}

// ---------------------------------------------------------------------------
// Fused 1x1 convs as batched GEMM (unchanged from the 1293us baseline).
// ---------------------------------------------------------------------------
__global__ __launch_bounds__(256)
void conv1x1_fused(const float* __restrict__ g,       const float* __restrict__ gwT,
                   const float* __restrict__ x,       const float* __restrict__ xwT,
                   const float* __restrict__ contour, const float* __restrict__ cwT,
                   float* __restrict__ zout, float* __restrict__ pout)
{
    __shared__ float sW[16 * 128];
    __shared__ float sI[16 * 128];

    const int tid = threadIdx.x;
    const int tx = tid & 15;
    const int ty = tid >> 4;
    const int pT = blockIdx.x * 128;
    const int b  = blockIdx.z;
    const int isZ = (blockIdx.y < 4);
    const int oT  = (isZ ? blockIdx.y : blockIdx.y - 4) * 128;

    const float* inA = isZ ? g   : contour;
    const float* wAT = isZ ? gwT : cwT;
    const int KA     = 256;
    const int doRelu = isZ;
    const float* inB = isZ ? x   : (const float*)0;
    const float* wBT = isZ ? xwT : (const float*)0;
    const int KB     = isZ ? 512 : 0;
    float* out       = isZ ? zout : pout;

    unsigned long long acc[8][4];
#pragma unroll
    for (int i = 0; i < 8; i++)
#pragma unroll
        for (int j = 0; j < 4; j++) acc[i][j] = 0ull;

#pragma unroll 1
    for (int pass = 0; pass < 2; pass++) {
        const float* in = pass ? inB : inA;
        const float* wT = pass ? wBT : wAT;
        const int K = pass ? KB : KA;
        if (K == 0) break;
        const float* inb = in + (size_t)b * K * HW;

#pragma unroll 1
        for (int k0 = 0; k0 < K; k0 += 16) {
            __syncthreads();
#pragma unroll
            for (int r = 0; r < 2; r++) {
                int lin = tid + r * 256;
                int kl = lin >> 5;
                int c4 = (lin & 31) * 4;
                *(float4*)&sW[kl * 128 + c4] = *(const float4*)&wT[(k0 + kl) * 512 + oT + c4];
                *(float4*)&sI[kl * 128 + c4] = *(const float4*)&inb[(size_t)(k0 + kl) * HW + pT + c4];
            }
            __syncthreads();
#pragma unroll
            for (int kk = 0; kk < 16; kk++) {
                float4 a0 = *(float4*)&sW[kk * 128 + ty * 8];
                float4 a1 = *(float4*)&sW[kk * 128 + ty * 8 + 4];
                float av[8] = {a0.x, a0.y, a0.z, a0.w, a1.x, a1.y, a1.z, a1.w};
                const ulonglong2* bp = (const ulonglong2*)&sI[kk * 128 + tx * 8];
                ulonglong2 b01 = bp[0];
                ulonglong2 b23 = bp[1];
                unsigned long long bv[4] = {b01.x, b01.y, b23.x, b23.y};
#pragma unroll
                for (int i = 0; i < 8; i++) {
                    unsigned long long ai = pack2(av[i], av[i]);
#pragma unroll
                    for (int j = 0; j < 4; j++)
                        fma2(acc[i][j], ai, bv[j]);
                }
            }
        }
        if (pass == 0 && doRelu) {
#pragma unroll
            for (int i = 0; i < 8; i++)
#pragma unroll
                for (int j = 0; j < 4; j++) {
                    float lo, hi;
                    unpack2(acc[i][j], lo, hi);
                    acc[i][j] = pack2(fmaxf(lo, 0.f), fmaxf(hi, 0.f));
                }
        }
    }

#pragma unroll
    for (int i = 0; i < 8; i++) {
        int o = oT + ty * 8 + i;
        float* orow = out + ((size_t)b * OCH + o) * HW + pT + tx * 8;
        ulonglong2 s0; s0.x = acc[i][0]; s0.y = acc[i][1];
        ulonglong2 s1; s1.x = acc[i][2]; s1.y = acc[i][3];
        *(ulonglong2*)&orow[0] = s0;
        *(ulonglong2*)&orow[4] = s1;
    }
}

// ---------------------------------------------------------------------------
// Block reductions over 256 threads (8 warps)
// ---------------------------------------------------------------------------
__device__ __forceinline__ float breduce1(float v, float* red) {
#pragma unroll
    for (int o = 16; o; o >>= 1) v += __shfl_xor_sync(0xffffffffu, v, o);
    int w = threadIdx.x >> 5;
    __syncthreads();
    if ((threadIdx.x & 31) == 0) red[w] = v;
    __syncthreads();
    float s = 0.f;
#pragma unroll
    for (int i = 0; i < 8; i++) s += red[i];
    return s;
}

__device__ __forceinline__ void breduce2(float& a, float& b, float* red) {
#pragma unroll
    for (int o = 16; o; o >>= 1) {
        a += __shfl_xor_sync(0xffffffffu, a, o);
        b += __shfl_xor_sync(0xffffffffu, b, o);
    }
    int w = threadIdx.x >> 5;
    __syncthreads();              // also the cross-iteration phi hazard barrier
    if ((threadIdx.x & 31) == 0) { red[w] = a; red[w + 8] = b; }
    __syncthreads();
    float sa = 0.f, sb = 0.f;
#pragma unroll
    for (int i = 0; i < 8; i++) { sa += red[i]; sb += red[i + 8]; }
    a = sa; b = sb;
}

// ---------------------------------------------------------------------------
// Chan-Vese, row-contiguous ownership: thread owns 16 consecutive pixels of
// one row (4 threads/row). Lane mapping seg=lane>>3, row=warp*8+(lane&7) makes
// each LDS.128 quarter-warp phase span 8 distinct rows; with a 68-float row
// stride the bank start 4*row mod 32 tiles all banks -> conflict-free vector
// smem access. phi & z own pixels live in registers; nx never touches smem
// (registers + 2 shuffles for segment boundaries); smem holds phi & ny planes
// only for VERTICAL neighbor reads. ~10x fewer smem instructions than the
// column-strip layout. jnp.gradient: clamped neighbor + scale.
// ---------------------------------------------------------------------------
#define RSTR 68   // row stride in floats (64 data + 4 pad)

__global__ __launch_bounds__(256)
void cv_kernel(const float* __restrict__ phi0, const float* __restrict__ z,
               const float* __restrict__ dtp, const float* __restrict__ lamp,
               float* __restrict__ out)
{
    __shared__ float phi_s[64 * RSTR];
    __shared__ float ny_s [64 * RSTR];
    __shared__ float red  [16];

    const int tid  = threadIdx.x;
    const int lane = tid & 31;
    const int warp = tid >> 5;
    const int seg  = lane >> 3;            // 0..3 (16-col segment)
    const int row  = warp * 8 + (lane & 7);// 0..63
    const int col0 = seg * 16;
    const size_t gbase = (size_t)blockIdx.x * HW + row * 64 + col0;
    const int sbase = row * RSTR + col0;

    const float dt  = dtp[0];
    const float lam = lamp[0];
    const float INV_PI = 0.3183098861837907f;

    const int rup = (row < 63) ? row + 1 : 63;   // clamped vertical neighbors
    const int rdn = (row > 0)  ? row - 1 : 0;
    const float sy = (row == 0 || row == 63) ? 1.f : 0.5f;

    float pr[16], zr[16], nxr[16];

    // ---- init: load phi0 & z (registers), publish phi to smem ----
    float sI = 0.f;
#pragma unroll
    for (int q = 0; q < 4; q++) {
        float4 pv = *(const float4*)&phi0[gbase + 4 * q];
        float4 zv = *(const float4*)&z   [gbase + 4 * q];
        pr[4*q+0] = pv.x; pr[4*q+1] = pv.y; pr[4*q+2] = pv.z; pr[4*q+3] = pv.w;
        zr[4*q+0] = zv.x; zr[4*q+1] = zv.y; zr[4*q+2] = zv.z; zr[4*q+3] = zv.w;
        sI += zv.x + zv.y + zv.z + zv.w;
        *(float4*)&phi_s[sbase + 4 * q] = pv;
    }
    float sumI = breduce1(sI, red);   // syncs also publish phi_s

#pragma unroll 1
    for (int it = 0; it < 10; it++) {
        // ---- region statistics (registers only) ----
        float sH = 0.f, sIH = 0.f;
#pragma unroll
        for (int c = 0; c < 16; c++) {
            float Hh = fmaf(INV_PI, atanf(pr[c]), 0.5f);
            sH  += Hh;
            sIH += zr[c] * Hh;
        }
        breduce2(sH, sIH, red);
        float c1 = sIH / (sH + 1e-8f);
        float c2 = (sumI - sIH) / (4096.0f - sH + 1e-8f);
        float A  = 2.0f * lam * (c1 - c2);
        float Bc = lam * (c2 * c2 - c1 * c1);

        // ---- pass B: normalized gradient; nx->regs, ny->smem ----
        float phiL = __shfl_sync(0xffffffffu, pr[15], (lane + 24) & 31); // left seg's last
        float phiR = __shfl_sync(0xffffffffu, pr[0],  (lane + 8)  & 31); // right seg's first
#pragma unroll
        for (int q = 0; q < 4; q++) {
            float4 u = *(float4*)&phi_s[rup * RSTR + col0 + 4 * q];
            float4 d = *(float4*)&phi_s[rdn * RSTR + col0 + 4 * q];
            float uu[4] = {u.x, u.y, u.z, u.w};
            float dd[4] = {d.x, d.y, d.z, d.w};
            float4 nyq;
            float* nyp = (float*)&nyq;
#pragma unroll
            for (int j = 0; j < 4; j++) {
                int c = 4 * q + j;
                int gc = col0 + c;
                float l = (c > 0)  ? pr[c - 1] : ((seg > 0) ? phiL : pr[0]);
                float r = (c < 15) ? pr[c + 1] : ((seg < 3) ? phiR : pr[15]);
                float sx = (gc == 0 || gc == 63) ? 1.f : 0.5f;
                float px = sx * (r - l);
                float py = sy * (uu[j] - dd[j]);
                float inv = rsqrtf(fmaf(px, px, fmaf(py, py, 1e-8f)));
                nxr[c] = px * inv;
                nyp[j] = py * inv;
            }
            *(float4*)&ny_s[sbase + 4 * q] = nyq;
        }
        __syncthreads();   // ny visible to vertical neighbors

        // ---- pass C: curvature + update (phi regs), publish phi to smem ----
        float nxL = __shfl_sync(0xffffffffu, nxr[15], (lane + 24) & 31);
        float nxR = __shfl_sync(0xffffffffu, nxr[0],  (lane + 8)  & 31);
#pragma unroll
        for (int q = 0; q < 4; q++) {
            float4 u = *(float4*)&ny_s[rup * RSTR + col0 + 4 * q];
            float4 d = *(float4*)&ny_s[rdn * RSTR + col0 + 4 * q];
            float uu[4] = {u.x, u.y, u.z, u.w};
            float dd[4] = {d.x, d.y, d.z, d.w};
#pragma unroll
            for (int j = 0; j < 4; j++) {
                int c = 4 * q + j;
                int gc = col0 + c;
                float l = (c > 0)  ? nxr[c - 1] : ((seg > 0) ? nxL : nxr[0]);
                float r = (c < 15) ? nxr[c + 1] : ((seg < 3) ? nxR : nxr[15]);
                float sx = (gc == 0 || gc == 63) ? 1.f : 0.5f;
                float curv = sx * (r - l) + sy * (uu[j] - dd[j]);
                float delta = INV_PI / fmaf(pr[c], pr[c], 1.0f);   // EPS_H = 1
                float force = curv + fmaf(A, zr[c], Bc);
                pr[c] = fmaf(dt * delta, force, pr[c]);
            }
        }
#pragma unroll
        for (int q = 0; q < 4; q++) {
            float4 pv = make_float4(pr[4*q+0], pr[4*q+1], pr[4*q+2], pr[4*q+3]);
            *(float4*)&phi_s[sbase + 4 * q] = pv;
        }
        // next iteration's breduce2 syncs separate this phi_s write from the
        // next pass B's neighbor reads.
    }

    // ---- sigmoid + store ----
#pragma unroll
    for (int q = 0; q < 4; q++) {
        float4 ov;
        ov.x = 1.0f / (1.0f + expf(-pr[4*q+0]));
        ov.y = 1.0f / (1.0f + expf(-pr[4*q+1]));
        ov.z = 1.0f / (1.0f + expf(-pr[4*q+2]));
        ov.w = 1.0f / (1.0f + expf(-pr[4*q+3]));
        *(float4*)&out[gbase + 4 * q] = ov;
    }
}

// ---------------------------------------------------------------------------
// Launch
// ---------------------------------------------------------------------------
extern "C" void kernel_launch(void* const* d_in, const int* in_sizes, int n_in,
                              void* d_out, int out_size)
{
    const float* contour = (const float*)d_in[0];   // [8,256,64,64]
    const float* g       = (const float*)d_in[1];   // [8,256,64,64]
    const float* x       = (const float*)d_in[2];   // [8,512,64,64]
    const float* dt      = (const float*)d_in[3];   // [1]
    const float* lam     = (const float*)d_in[4];   // [1]
    const float* g_w     = (const float*)d_in[5];   // [512,256]
    const float* x_w     = (const float*)d_in[6];   // [512,512]
    const float* c_w     = (const float*)d_in[7];   // [512,256]
    float* out = (float*)d_out;                     // [8,512,64,64]

    float *zbuf, *phibuf, *gwT, *xwT, *cwT;
    cudaGetSymbolAddress((void**)&zbuf,   g_z);
    cudaGetSymbolAddress((void**)&phibuf, g_phi);
    cudaGetSymbolAddress((void**)&gwT,    g_gwT);
    cudaGetSymbolAddress((void**)&xwT,    g_xwT);
    cudaGetSymbolAddress((void**)&cwT,    g_cwT);

    dim3 tgrid((512 * 512 + 255) / 256, 3);
    transpose_w_all<<<tgrid, 256>>>(g_w, x_w, c_w, gwT, xwT, cwT);

    dim3 grid(HW / 128, 8, BATCH);   // 32 x 8 x 8 = 2048 CTAs
    conv1x1_fused<<<grid, 256>>>(g, gwT, x, xwT, contour, cwT, zbuf, phibuf);

    cv_kernel<<<NPLANES, 256>>>(phibuf, zbuf, dt, lam, out);
}